// round 1
// baseline (speedup 1.0000x reference)
#include <cuda_runtime.h>

#define NC 10
#define D  64

// cc result handed from the iterative kernel to the per-slot MLP kernel.
__device__ float g_cc[NC * D];

__device__ __forceinline__ float sigmoidf_(float x) {
    return 1.0f / (1.0f + __expf(-x));
}

// ---------------------------------------------------------------------------
// Kernel 1: the 3-iteration slot-attention / GRU / MLP core. One block,
// 640 threads = (n, i) over the [10, 64] state. All state in shared memory.
// ---------------------------------------------------------------------------
__global__ void __launch_bounds__(640)
slot_iter_kernel(
    const float* __restrict__ cc0,
    const float* __restrict__ Wk, const float* __restrict__ bk,
    const float* __restrict__ Wq, const float* __restrict__ bq,
    const float* __restrict__ Wv, const float* __restrict__ bv,
    const float* __restrict__ cc_g, const float* __restrict__ cc_b,
    const float* __restrict__ W_ih, const float* __restrict__ W_hh,
    const float* __restrict__ b_ih, const float* __restrict__ b_hh,
    const float* __restrict__ ln_g, const float* __restrict__ ln_b,
    const float* __restrict__ W1, const float* __restrict__ b1,
    const float* __restrict__ W2, const float* __restrict__ b2)
{
    __shared__ float s_cc[NC][D];
    __shared__ float s_k[NC][D];
    __shared__ float s_v[NC][D];
    __shared__ float s_tmp[NC][D];    // LN output, then attn updates, then LN2 output
    __shared__ float s_q[NC][D];
    __shared__ float s_attn[NC][NC];
    __shared__ float s_gi[NC][3 * D];
    __shared__ float s_gh[NC][3 * D];
    __shared__ float s_h2[NC][2 * D];
    __shared__ float s_new[NC][D];
    __shared__ float s_mean[NC], s_rstd[NC];

    const int tid = threadIdx.x;          // 0..639
    const int n = tid >> 6;               // cluster row 0..9
    const int i = tid & 63;               // feature   0..63

    s_cc[n][i] = cc0[tid];
    __syncthreads();

    // k = cc0 @ Wk.T + bk ; v = cc0 @ Wv.T + bv
    {
        float ak = bk[i], av = bv[i];
        #pragma unroll 8
        for (int j = 0; j < D; j++) {
            float c = s_cc[n][j];
            ak = fmaf(c, Wk[i * D + j], ak);
            av = fmaf(c, Wv[i * D + j], av);
        }
        s_k[n][i] = ak;
        s_v[n][i] = av;
    }

    for (int it = 0; it < 3; it++) {
        __syncthreads();   // covers s_k/s_v writes (it=0) and s_cc writes (it>0)

        // LayerNorm(cc) stats with cc_g / cc_b
        if (tid < NC) {
            float s = 0.f, s2 = 0.f;
            for (int j = 0; j < D; j++) {
                float x = s_cc[tid][j];
                s += x; s2 += x * x;
            }
            float m = s * (1.0f / D);
            float var = s2 * (1.0f / D) - m * m;
            s_mean[tid] = m;
            s_rstd[tid] = rsqrtf(var + 1e-5f);
        }
        __syncthreads();
        s_tmp[n][i] = (s_cc[n][i] - s_mean[n]) * s_rstd[n] * cc_g[i] + cc_b[i];
        __syncthreads();

        // q = LN(cc) @ Wq.T + bq
        {
            float aq = bq[i];
            #pragma unroll 8
            for (int j = 0; j < D; j++)
                aq = fmaf(s_tmp[n][j], Wq[i * D + j], aq);
            s_q[n][i] = aq;
        }
        __syncthreads();

        // attn[an][am] = (k[an] . q[am]) * d^-0.5
        if (tid < NC * NC) {
            int an = tid / NC, am = tid % NC;
            float a = 0.f;
            #pragma unroll 8
            for (int j = 0; j < D; j++)
                a = fmaf(s_k[an][j], s_q[am][j], a);
            s_attn[an][am] = a * 0.125f;
        }
        __syncthreads();

        // softmax over axis 0 (per column m), + EPS
        if (tid < NC) {
            int m = tid;
            float mx = s_attn[0][m];
            #pragma unroll
            for (int r = 1; r < NC; r++) mx = fmaxf(mx, s_attn[r][m]);
            float e[NC];
            float sum = 0.f;
            #pragma unroll
            for (int r = 0; r < NC; r++) { e[r] = __expf(s_attn[r][m] - mx); sum += e[r]; }
            float inv = 1.0f / sum;
            #pragma unroll
            for (int r = 0; r < NC; r++) s_attn[r][m] = e[r] * inv + 1e-8f;
        }
        __syncthreads();

        // row normalization (per row n)
        if (tid < NC) {
            int r = tid;
            float sum = 0.f;
            #pragma unroll
            for (int m = 0; m < NC; m++) sum += s_attn[r][m];
            float inv = 1.0f / sum;
            #pragma unroll
            for (int m = 0; m < NC; m++) s_attn[r][m] *= inv;
        }
        __syncthreads();

        // updates = attn @ v
        {
            float u = 0.f;
            #pragma unroll
            for (int m = 0; m < NC; m++)
                u = fmaf(s_attn[n][m], s_v[m][i], u);
            s_tmp[n][i] = u;
        }
        __syncthreads();

        // GRU gates: gi = updates @ W_ih.T + b_ih ; gh = cc_prev @ W_hh.T + b_hh
        for (int e = tid; e < NC * 3 * D; e += 640) {
            int rn = e / (3 * D), c = e % (3 * D);
            float a = b_ih[c], ah = b_hh[c];
            #pragma unroll 8
            for (int j = 0; j < D; j++) {
                a  = fmaf(s_tmp[rn][j], W_ih[c * D + j], a);
                ah = fmaf(s_cc[rn][j],  W_hh[c * D + j], ah);
            }
            s_gi[rn][c] = a;
            s_gh[rn][c] = ah;
        }
        __syncthreads();

        // GRU elementwise
        {
            float r  = sigmoidf_(s_gi[n][i]       + s_gh[n][i]);
            float z  = sigmoidf_(s_gi[n][D + i]   + s_gh[n][D + i]);
            float nn = tanhf(s_gi[n][2 * D + i] + r * s_gh[n][2 * D + i]);
            s_new[n][i] = (1.0f - z) * nn + z * s_cc[n][i];
        }
        __syncthreads();

        // LayerNorm(cc_new) with ln_g / ln_b
        if (tid < NC) {
            float s = 0.f, s2 = 0.f;
            for (int j = 0; j < D; j++) {
                float x = s_new[tid][j];
                s += x; s2 += x * x;
            }
            float m = s * (1.0f / D);
            float var = s2 * (1.0f / D) - m * m;
            s_mean[tid] = m;
            s_rstd[tid] = rsqrtf(var + 1e-5f);
        }
        __syncthreads();
        s_tmp[n][i] = (s_new[n][i] - s_mean[n]) * s_rstd[n] * ln_g[i] + ln_b[i];
        __syncthreads();

        // h2 = relu(LN @ W1.T + b1)   [10, 128]
        for (int e = tid; e < NC * 2 * D; e += 640) {
            int rn = e / (2 * D), c = e % (2 * D);
            float a = b1[c];
            #pragma unroll 8
            for (int j = 0; j < D; j++)
                a = fmaf(s_tmp[rn][j], W1[c * D + j], a);
            s_h2[rn][c] = fmaxf(a, 0.f);
        }
        __syncthreads();

        // cc = cc_new + h2 @ W2.T + b2
        {
            float a = b2[i];
            #pragma unroll 8
            for (int j = 0; j < 2 * D; j++)
                a = fmaf(s_h2[n][j], W2[i * 2 * D + j], a);
            s_cc[n][i] = s_new[n][i] + a;
        }
    }
    __syncthreads();
    g_cc[tid] = s_cc[n][i];
}

// ---------------------------------------------------------------------------
// Kernel 2: per-slot 2-layer MLP + max over the 10 clusters.
// 4 slots per 256-thread block; thread i owns output feature i of its slot.
// Streams Wa/Wb rows (LDG.128); cc/h in smem (all reads warp-uniform).
// ---------------------------------------------------------------------------
__global__ void __launch_bounds__(256)
slot_mlp_kernel(
    const float* __restrict__ Wa, const float* __restrict__ ba,
    const float* __restrict__ Wb, const float* __restrict__ bb,
    float* __restrict__ out)
{
    __shared__ float cc_s[NC][D];
    __shared__ float h_s[4][NC][D];

    const int tid = threadIdx.x;
    for (int t = tid; t < NC * D; t += 256)
        ((float*)cc_s)[t] = g_cc[t];
    __syncthreads();

    const int sl = tid >> 6;          // slot within block 0..3
    const int i  = tid & 63;          // output feature
    const int slot = (blockIdx.x << 2) + sl;

    float acc[NC];

    // Stage 1: h[n][i] = relu(sum_j Wa[slot][i][j] * cc[n][j] + ba[slot][i])
    {
        const float4* wrow = (const float4*)(Wa + (size_t)slot * (D * D) + i * D);
        float bias = ba[slot * D + i];
        #pragma unroll
        for (int n = 0; n < NC; n++) acc[n] = bias;
        #pragma unroll
        for (int j4 = 0; j4 < D / 4; j4++) {
            float4 w = __ldg(&wrow[j4]);
            #pragma unroll
            for (int n = 0; n < NC; n++) {
                float4 c = *(const float4*)&cc_s[n][j4 * 4];
                acc[n] = fmaf(w.x, c.x, acc[n]);
                acc[n] = fmaf(w.y, c.y, acc[n]);
                acc[n] = fmaf(w.z, c.z, acc[n]);
                acc[n] = fmaf(w.w, c.w, acc[n]);
            }
        }
        #pragma unroll
        for (int n = 0; n < NC; n++)
            h_s[sl][n][i] = fmaxf(acc[n], 0.f);
    }
    __syncthreads();

    // Stage 2: out[n][i] = sum_j Wb[slot][i][j] * h[n][j] + bb[slot][i]; max over n
    {
        const float4* wrow = (const float4*)(Wb + (size_t)slot * (D * D) + i * D);
        float bias = bb[slot * D + i];
        #pragma unroll
        for (int n = 0; n < NC; n++) acc[n] = bias;
        #pragma unroll
        for (int j4 = 0; j4 < D / 4; j4++) {
            float4 w = __ldg(&wrow[j4]);
            #pragma unroll
            for (int n = 0; n < NC; n++) {
                float4 h = *(const float4*)&h_s[sl][n][j4 * 4];
                acc[n] = fmaf(w.x, h.x, acc[n]);
                acc[n] = fmaf(w.y, h.y, acc[n]);
                acc[n] = fmaf(w.z, h.z, acc[n]);
                acc[n] = fmaf(w.w, h.w, acc[n]);
            }
        }
        float m = acc[0];
        #pragma unroll
        for (int n = 1; n < NC; n++) m = fmaxf(m, acc[n]);
        out[slot * D + i] = m;
    }
}

// ---------------------------------------------------------------------------
extern "C" void kernel_launch(void* const* d_in, const int* in_sizes, int n_in,
                              void* d_out, int out_size)
{
    const float* cc0  = (const float*)d_in[0];
    const float* Wk   = (const float*)d_in[1];
    const float* bk   = (const float*)d_in[2];
    const float* Wq   = (const float*)d_in[3];
    const float* bq   = (const float*)d_in[4];
    const float* Wv   = (const float*)d_in[5];
    const float* bv   = (const float*)d_in[6];
    const float* cc_g = (const float*)d_in[7];
    const float* cc_b = (const float*)d_in[8];
    const float* W_ih = (const float*)d_in[9];
    const float* W_hh = (const float*)d_in[10];
    const float* b_ih = (const float*)d_in[11];
    const float* b_hh = (const float*)d_in[12];
    const float* ln_g = (const float*)d_in[13];
    const float* ln_b = (const float*)d_in[14];
    const float* W1   = (const float*)d_in[15];
    const float* b1   = (const float*)d_in[16];
    const float* W2   = (const float*)d_in[17];
    const float* b2   = (const float*)d_in[18];
    const float* Wa   = (const float*)d_in[19];
    const float* ba   = (const float*)d_in[20];
    const float* Wb   = (const float*)d_in[21];
    const float* bb   = (const float*)d_in[22];

    slot_iter_kernel<<<1, 640>>>(cc0, Wk, bk, Wq, bq, Wv, bv, cc_g, cc_b,
                                 W_ih, W_hh, b_ih, b_hh, ln_g, ln_b,
                                 W1, b1, W2, b2);
    slot_mlp_kernel<<<4096 / 4, 256>>>(Wa, ba, Wb, bb, (float*)d_out);
}

// round 2
// speedup vs baseline: 6.1059x; 6.1059x over previous
#include <cuda_runtime.h>
#include <cstdint>

#define NC 10
#define D  64

__device__ float g_cc[NC * D];

__device__ __forceinline__ float sigmoidf_(float x) {
    return 1.0f / (1.0f + __expf(-x));
}

__device__ __forceinline__ void cp_async16(uint32_t smem_addr, const void* gptr) {
    asm volatile("cp.async.cg.shared.global [%0], [%1], 16;\n"
                 :: "r"(smem_addr), "l"(gptr));
}
__device__ __forceinline__ void cp_commit() {
    asm volatile("cp.async.commit_group;\n");
}
template <int N>
__device__ __forceinline__ void cp_wait() {
    asm volatile("cp.async.wait_group %0;\n" :: "n"(N));
}

// ---------------------------------------------------------------------------
// Kernel 1: 3-iteration slot-attention core. One block, 640 threads.
// All recurring weights staged ONCE into dynamic smem, transposed with a
// +1 column pad: WT[j][c] at buf[j*(C+1)+c]. Global reads coalesced; smem
// compute reads are lane-consecutive in c -> conflict-free.
// Dynamic smem layout (floats):
//   WqT  @ 0      : 64*65   = 4160
//   WihT @ 4160   : 64*193  = 12352
//   WhhT @ 16512  : 64*193  = 12352
//   W1T  @ 28864  : 64*129  = 8256
//   W2T  @ 37120  : 128*65  = 8320   (W2 is [64][128] -> WT[j][i], j<128)
//   total 45440 floats = 181760 bytes
// ---------------------------------------------------------------------------
#define OFF_WQ  0
#define OFF_WIH 4160
#define OFF_WHH 16512
#define OFF_W1  28864
#define OFF_W2  37120
#define K1_DYN_BYTES (45440 * 4)

__global__ void __launch_bounds__(640, 1)
slot_iter_kernel(
    const float* __restrict__ cc0,
    const float* __restrict__ Wk, const float* __restrict__ bk,
    const float* __restrict__ Wq, const float* __restrict__ bq,
    const float* __restrict__ Wv, const float* __restrict__ bv,
    const float* __restrict__ cc_g, const float* __restrict__ cc_b,
    const float* __restrict__ W_ih, const float* __restrict__ W_hh,
    const float* __restrict__ b_ih, const float* __restrict__ b_hh,
    const float* __restrict__ ln_g, const float* __restrict__ ln_b,
    const float* __restrict__ W1, const float* __restrict__ b1,
    const float* __restrict__ W2, const float* __restrict__ b2)
{
    extern __shared__ float dyn[];

    __shared__ float s_cc[NC][D];
    __shared__ float s_k[NC][D];
    __shared__ float s_v[NC][D];
    __shared__ float s_tmp[NC][D];
    __shared__ float s_q[NC][D];
    __shared__ float s_new[NC][D];
    __shared__ float s_attn[NC][NC];
    __shared__ float s_gi[NC][3 * D];
    __shared__ float s_gh[NC][3 * D];
    __shared__ float s_h2[NC][2 * D];
    __shared__ float s_mean[NC], s_rstd[NC];
    __shared__ float s_p1[20], s_p2[20];

    const int tid = threadIdx.x;
    const int n = tid >> 6;
    const int i = tid & 63;
    const int warp = tid >> 5;
    const int lane = tid & 31;

    // stage [C x 64] row-major W into buf as WT[j][c] with pad C+1
    auto stageT = [&](const float* __restrict__ W, float* buf, int C) {
        int Cp = C + 1;
        for (int e = tid; e < C * 64; e += 640) {
            int c = e >> 6, j = e & 63;
            buf[j * Cp + c] = W[e];
        }
    };

    s_cc[n][i] = cc0[tid];
    // temporary: WkT -> WQ slot, WvT -> WIH slot
    stageT(Wk, dyn + OFF_WQ, 64);
    stageT(Wv, dyn + OFF_WIH, 64);
    __syncthreads();

    // k = cc0 @ Wk.T + bk ; v = cc0 @ Wv.T + bv
    {
        float ak = bk[i], av = bv[i];
        const float* wk = dyn + OFF_WQ;
        const float* wv = dyn + OFF_WIH;
        #pragma unroll 8
        for (int j = 0; j < D; j++) {
            float c = s_cc[n][j];
            ak = fmaf(c, wk[j * 65 + i], ak);
            av = fmaf(c, wv[j * 65 + i], av);
        }
        s_k[n][i] = ak;
        s_v[n][i] = av;
    }
    __syncthreads();

    // stage the recurring weights (overwrite temporaries)
    stageT(Wq,   dyn + OFF_WQ,  64);
    stageT(W_ih, dyn + OFF_WIH, 192);
    stageT(W_hh, dyn + OFF_WHH, 192);
    stageT(W1,   dyn + OFF_W1,  128);
    // W2 is [64][128]: e = i*128 + j -> WT[j][i] pad 65
    for (int e = tid; e < 64 * 128; e += 640) {
        int r = e >> 7, j = e & 127;
        (dyn + OFF_W2)[j * 65 + r] = W2[e];
    }

    for (int it = 0; it < 3; it++) {
        __syncthreads();

        // LayerNorm(cc) stats: warp shuffle + 2-partial combine
        {
            float x = s_cc[n][i];
            float s = x, s2 = x * x;
            #pragma unroll
            for (int o = 16; o; o >>= 1) {
                s  += __shfl_down_sync(0xffffffffu, s,  o);
                s2 += __shfl_down_sync(0xffffffffu, s2, o);
            }
            if (lane == 0) { s_p1[warp] = s; s_p2[warp] = s2; }
            __syncthreads();
            if (tid < NC) {
                float ss  = s_p1[2 * tid] + s_p1[2 * tid + 1];
                float ss2 = s_p2[2 * tid] + s_p2[2 * tid + 1];
                float m = ss * (1.0f / D);
                float var = ss2 * (1.0f / D) - m * m;
                s_mean[tid] = m;
                s_rstd[tid] = rsqrtf(var + 1e-5f);
            }
            __syncthreads();
            s_tmp[n][i] = (s_cc[n][i] - s_mean[n]) * s_rstd[n] * cc_g[i] + cc_b[i];
        }
        __syncthreads();

        // q = LN(cc) @ Wq.T + bq
        {
            float aq = bq[i];
            const float* wq = dyn + OFF_WQ;
            #pragma unroll 8
            for (int j = 0; j < D; j++)
                aq = fmaf(s_tmp[n][j], wq[j * 65 + i], aq);
            s_q[n][i] = aq;
        }
        __syncthreads();

        // attn[an][am] = (k[an] . q[am]) * d^-0.5
        if (tid < NC * NC) {
            int an = tid / NC, am = tid % NC;
            float a = 0.f;
            #pragma unroll 8
            for (int j = 0; j < D; j++)
                a = fmaf(s_k[an][j], s_q[am][j], a);
            s_attn[an][am] = a * 0.125f;
        }
        __syncthreads();

        // softmax over axis 0 (per column m), + EPS
        if (tid < NC) {
            int m = tid;
            float mx = s_attn[0][m];
            #pragma unroll
            for (int r = 1; r < NC; r++) mx = fmaxf(mx, s_attn[r][m]);
            float e[NC];
            float sum = 0.f;
            #pragma unroll
            for (int r = 0; r < NC; r++) { e[r] = __expf(s_attn[r][m] - mx); sum += e[r]; }
            float inv = 1.0f / sum;
            #pragma unroll
            for (int r = 0; r < NC; r++) s_attn[r][m] = e[r] * inv + 1e-8f;
        }
        __syncthreads();

        // row normalization (per row n)
        if (tid < NC) {
            int r = tid;
            float sum = 0.f;
            #pragma unroll
            for (int m = 0; m < NC; m++) sum += s_attn[r][m];
            float inv = 1.0f / sum;
            #pragma unroll
            for (int m = 0; m < NC; m++) s_attn[r][m] *= inv;
        }
        __syncthreads();

        // updates = attn @ v
        {
            float u = 0.f;
            #pragma unroll
            for (int m = 0; m < NC; m++)
                u = fmaf(s_attn[n][m], s_v[m][i], u);
            s_tmp[n][i] = u;
        }
        __syncthreads();

        // GRU gates
        {
            const float* wih = dyn + OFF_WIH;
            const float* whh = dyn + OFF_WHH;
            for (int e = tid; e < NC * 3 * D; e += 640) {
                int rn = e / (3 * D), c = e % (3 * D);
                float a = b_ih[c], ah = b_hh[c];
                #pragma unroll 8
                for (int j = 0; j < D; j++) {
                    a  = fmaf(s_tmp[rn][j], wih[j * 193 + c], a);
                    ah = fmaf(s_cc[rn][j],  whh[j * 193 + c], ah);
                }
                s_gi[rn][c] = a;
                s_gh[rn][c] = ah;
            }
        }
        __syncthreads();

        // GRU elementwise
        {
            float r  = sigmoidf_(s_gi[n][i]     + s_gh[n][i]);
            float z  = sigmoidf_(s_gi[n][D + i] + s_gh[n][D + i]);
            float nn = tanhf(s_gi[n][2 * D + i] + r * s_gh[n][2 * D + i]);
            s_new[n][i] = (1.0f - z) * nn + z * s_cc[n][i];
        }
        __syncthreads();

        // LayerNorm(cc_new)
        {
            float x = s_new[n][i];
            float s = x, s2 = x * x;
            #pragma unroll
            for (int o = 16; o; o >>= 1) {
                s  += __shfl_down_sync(0xffffffffu, s,  o);
                s2 += __shfl_down_sync(0xffffffffu, s2, o);
            }
            if (lane == 0) { s_p1[warp] = s; s_p2[warp] = s2; }
            __syncthreads();
            if (tid < NC) {
                float ss  = s_p1[2 * tid] + s_p1[2 * tid + 1];
                float ss2 = s_p2[2 * tid] + s_p2[2 * tid + 1];
                float m = ss * (1.0f / D);
                float var = ss2 * (1.0f / D) - m * m;
                s_mean[tid] = m;
                s_rstd[tid] = rsqrtf(var + 1e-5f);
            }
            __syncthreads();
            s_tmp[n][i] = (s_new[n][i] - s_mean[n]) * s_rstd[n] * ln_g[i] + ln_b[i];
        }
        __syncthreads();

        // h2 = relu(LN @ W1.T + b1)   [10, 128]
        {
            const float* w1 = dyn + OFF_W1;
            for (int e = tid; e < NC * 2 * D; e += 640) {
                int rn = e / (2 * D), c = e % (2 * D);
                float a = b1[c];
                #pragma unroll 8
                for (int j = 0; j < D; j++)
                    a = fmaf(s_tmp[rn][j], w1[j * 129 + c], a);
                s_h2[rn][c] = fmaxf(a, 0.f);
            }
        }
        __syncthreads();

        // cc = cc_new + h2 @ W2.T + b2
        {
            const float* w2 = dyn + OFF_W2;
            float a = b2[i];
            #pragma unroll 8
            for (int j = 0; j < 2 * D; j++)
                a = fmaf(s_h2[n][j], w2[j * 65 + i], a);
            s_cc[n][i] = s_new[n][i] + a;
        }
    }
    __syncthreads();
    g_cc[tid] = s_cc[n][i];
}

// ---------------------------------------------------------------------------
// Kernel 2: per-slot MLP + max. 2 slots / 128-thread block.
// Wa,Wb streamed via cp.async.cg (coalesced, L1-bypass) into padded smem
// rows (68 floats = 272B, 16B-aligned) -> conflict-free LDS.128 at compute.
// Wb prefetch overlaps stage-1 compute.
// Dynamic smem (floats):
//   wa @ 0      : 2*4352 = 8704
//   wb @ 8704   : 2*4352 = 8704
//   cc @ 17408  : 640
//   h  @ 18048  : 2*640 = 1280
//   total 19328 floats = 77312 bytes
// ---------------------------------------------------------------------------
#define K2_DYN_BYTES (19328 * 4)

__global__ void __launch_bounds__(128, 2)
slot_mlp_kernel(
    const float* __restrict__ Wa, const float* __restrict__ ba,
    const float* __restrict__ Wb, const float* __restrict__ bb,
    float* __restrict__ out)
{
    extern __shared__ float sm[];
    float* wa  = sm;
    float* wb  = sm + 8704;
    float* ccs = sm + 17408;
    float* hs  = sm + 18048;

    const int tid = threadIdx.x;
    const int slot0 = blockIdx.x * 2;

    // issue Wa copies (group depth 1 after Wb commit)
    #pragma unroll
    for (int sl = 0; sl < 2; sl++) {
        const char* gbase = (const char*)(Wa + (size_t)(slot0 + sl) * (D * D));
        uint32_t sbase = (uint32_t)__cvta_generic_to_shared(wa + sl * 4352);
        #pragma unroll
        for (int c = 0; c < 8; c++) {
            int ch = tid + c * 128;               // 0..1023
            int row = ch >> 4, q = ch & 15;
            cp_async16(sbase + row * 272 + q * 16, gbase + ch * 16);
        }
    }
    cp_commit();
    // issue Wb copies
    #pragma unroll
    for (int sl = 0; sl < 2; sl++) {
        const char* gbase = (const char*)(Wb + (size_t)(slot0 + sl) * (D * D));
        uint32_t sbase = (uint32_t)__cvta_generic_to_shared(wb + sl * 4352);
        #pragma unroll
        for (int c = 0; c < 8; c++) {
            int ch = tid + c * 128;
            int row = ch >> 4, q = ch & 15;
            cp_async16(sbase + row * 272 + q * 16, gbase + ch * 16);
        }
    }
    cp_commit();

    // cc from kernel 1
    for (int t = tid; t < NC * D; t += 128)
        ccs[t] = g_cc[t];

    const int sl = tid >> 6;
    const int i  = tid & 63;
    const int slot = slot0 + sl;

    float acc[NC];

    cp_wait<1>();          // Wa ready
    __syncthreads();

    // Stage 1: h[n][i] = relu(Wa[slot] row i . cc[n] + ba)
    {
        const float4* wrow = (const float4*)(wa + sl * 4352 + i * 68);
        float bias = ba[slot * D + i];
        #pragma unroll
        for (int n = 0; n < NC; n++) acc[n] = bias;
        #pragma unroll
        for (int j4 = 0; j4 < D / 4; j4++) {
            float4 w = wrow[j4];
            #pragma unroll
            for (int n = 0; n < NC; n++) {
                float4 c = *(const float4*)&ccs[n * D + j4 * 4];
                acc[n] = fmaf(w.x, c.x, acc[n]);
                acc[n] = fmaf(w.y, c.y, acc[n]);
                acc[n] = fmaf(w.z, c.z, acc[n]);
                acc[n] = fmaf(w.w, c.w, acc[n]);
            }
        }
        #pragma unroll
        for (int n = 0; n < NC; n++)
            hs[sl * 640 + n * D + i] = fmaxf(acc[n], 0.f);
    }

    cp_wait<0>();          // Wb ready
    __syncthreads();       // also publishes hs

    // Stage 2: out[n][i] = Wb[slot] row i . h[n] + bb; max over n
    {
        const float4* wrow = (const float4*)(wb + sl * 4352 + i * 68);
        float bias = bb[slot * D + i];
        #pragma unroll
        for (int n = 0; n < NC; n++) acc[n] = bias;
        #pragma unroll
        for (int j4 = 0; j4 < D / 4; j4++) {
            float4 w = wrow[j4];
            #pragma unroll
            for (int n = 0; n < NC; n++) {
                float4 h = *(const float4*)&hs[sl * 640 + n * D + j4 * 4];
                acc[n] = fmaf(w.x, h.x, acc[n]);
                acc[n] = fmaf(w.y, h.y, acc[n]);
                acc[n] = fmaf(w.z, h.z, acc[n]);
                acc[n] = fmaf(w.w, h.w, acc[n]);
            }
        }
        float m = acc[0];
        #pragma unroll
        for (int n = 1; n < NC; n++) m = fmaxf(m, acc[n]);
        out[slot * D + i] = m;
    }
}

// ---------------------------------------------------------------------------
extern "C" void kernel_launch(void* const* d_in, const int* in_sizes, int n_in,
                              void* d_out, int out_size)
{
    const float* cc0  = (const float*)d_in[0];
    const float* Wk   = (const float*)d_in[1];
    const float* bk   = (const float*)d_in[2];
    const float* Wq   = (const float*)d_in[3];
    const float* bq   = (const float*)d_in[4];
    const float* Wv   = (const float*)d_in[5];
    const float* bv   = (const float*)d_in[6];
    const float* cc_g = (const float*)d_in[7];
    const float* cc_b = (const float*)d_in[8];
    const float* W_ih = (const float*)d_in[9];
    const float* W_hh = (const float*)d_in[10];
    const float* b_ih = (const float*)d_in[11];
    const float* b_hh = (const float*)d_in[12];
    const float* ln_g = (const float*)d_in[13];
    const float* ln_b = (const float*)d_in[14];
    const float* W1   = (const float*)d_in[15];
    const float* b1   = (const float*)d_in[16];
    const float* W2   = (const float*)d_in[17];
    const float* b2   = (const float*)d_in[18];
    const float* Wa   = (const float*)d_in[19];
    const float* ba   = (const float*)d_in[20];
    const float* Wb   = (const float*)d_in[21];
    const float* bb   = (const float*)d_in[22];

    cudaFuncSetAttribute(slot_iter_kernel,
                         cudaFuncAttributeMaxDynamicSharedMemorySize, K1_DYN_BYTES);
    cudaFuncSetAttribute(slot_mlp_kernel,
                         cudaFuncAttributeMaxDynamicSharedMemorySize, K2_DYN_BYTES);

    slot_iter_kernel<<<1, 640, K1_DYN_BYTES>>>(cc0, Wk, bk, Wq, bq, Wv, bv,
                                               cc_g, cc_b, W_ih, W_hh, b_ih, b_hh,
                                               ln_g, ln_b, W1, b1, W2, b2);
    slot_mlp_kernel<<<4096 / 2, 128, K2_DYN_BYTES>>>(Wa, ba, Wb, bb, (float*)d_out);
}